// round 6
// baseline (speedup 1.0000x reference)
#include <cuda_runtime.h>
#include <cuda_bf16.h>
#include <math.h>

// Problem constants (match reference)
#define N_NODES_C  100000
#define N_EDGES_C  1600000
#define N_GRAPHS_C 1000
#define FDIM       100
#define FIN        336

// ---------------------------------------------------------------------------
// Scratch buffers (static __device__ globals — no runtime allocation)
// ---------------------------------------------------------------------------
__device__ __align__(16) float g_xw  [N_NODES_C * FDIM];   // x @ W for current layer
__device__ __align__(16) float g_aggA[N_NODES_C * FDIM];   // ping
__device__ __align__(16) float g_aggB[N_NODES_C * FDIM];   // pong
__device__ __align__(16) float g_deg [N_NODES_C];
__device__ __align__(16) float g_dinv[N_NODES_C];
__device__ __align__(16) float g_sums[N_GRAPHS_C * FDIM];
__device__ __align__(16) float g_cnt [N_GRAPHS_C];
__device__ __align__(16) float g_g1  [N_GRAPHS_C * FDIM];
__device__ __align__(16) float g_g2  [N_GRAPHS_C * FDIM];
__device__ __align__(16) int   g_erow[N_EDGES_C];
__device__ __align__(16) int   g_ecol[N_EDGES_C];
__device__ __align__(16) int   g_bat [N_NODES_C];
__device__ int g_is64;

// ---------------------------------------------------------------------------
// Index dtype detection + normalization to int32.
// If the buffer holds int64 values < 2^31 (all indices < 1e5), every odd
// int32 word is 0. For genuine int32 edge data (random in [0,1e5)), 64
// consecutive zero odd-words is impossible in practice.
// ---------------------------------------------------------------------------
__global__ void detect_kernel(const int* __restrict__ raw) {
    if (blockIdx.x == 0 && threadIdx.x == 0) {
        int s = 0;
        for (int i = 0; i < 64; i++) s |= raw[2 * i + 1];
        g_is64 = (s == 0) ? 1 : 0;
    }
}

__global__ void cvt_edges_kernel(const int* __restrict__ raw,
                                 int* __restrict__ erow,
                                 int* __restrict__ ecol) {
    int e = blockIdx.x * blockDim.x + threadIdx.x;
    if (e >= N_EDGES_C) return;
    if (g_is64) {   // little-endian low word of each int64
        erow[e] = raw[2 * e];
        ecol[e] = raw[2 * (N_EDGES_C + e)];
    } else {
        erow[e] = raw[e];
        ecol[e] = raw[N_EDGES_C + e];
    }
}

__global__ void cvt_batch_kernel(const int* __restrict__ raw,
                                 int* __restrict__ bat) {
    int i = blockIdx.x * blockDim.x + threadIdx.x;
    if (i >= N_NODES_C) return;
    bat[i] = g_is64 ? raw[2 * i] : raw[i];
}

// ---------------------------------------------------------------------------
// Small utility kernels
// ---------------------------------------------------------------------------
__global__ void zero_kernel(float* __restrict__ p, int n) {
    int i = blockIdx.x * blockDim.x + threadIdx.x;
    if (i < n) p[i] = 0.0f;
}

__global__ void deg_kernel(const int* __restrict__ ecol,
                           float* __restrict__ deg) {
    int e = blockIdx.x * blockDim.x + threadIdx.x;
    if (e < N_EDGES_C) atomicAdd(deg + ecol[e], 1.0f);
}

__global__ void dinv_kernel(const float* __restrict__ deg,
                            float* __restrict__ dinv) {
    int i = blockIdx.x * blockDim.x + threadIdx.x;
    if (i < N_NODES_C) dinv[i] = rsqrtf(deg[i] + 2.0f);
}

// ---------------------------------------------------------------------------
// GEMM:  xw[N,100] = f(A)[N,K] @ W[K,100]
//   f(A) = relu(A + bias_in)  when hasBias (fuses previous layer's bias+relu)
//   epilogue also writes aggOut = (2*dinv^2) * xw  (self-loop init term)
// Tiling: BM=128 rows, BN=100 (full), BK=4. 128 threads; thread (rg,cg)
// owns a 4x25 register tile (rows rg*4..+3, cols cg*25..+24).
// ---------------------------------------------------------------------------
__global__ __launch_bounds__(128)
void gemm_kernel(const float* __restrict__ A,
                 const float* __restrict__ W,
                 const float* __restrict__ bias_in,
                 const float* __restrict__ dinv,
                 float* __restrict__ xw,
                 float* __restrict__ aggOut,
                 int K, int hasBias)
{
    __shared__ __align__(16) float Ask[4][128];   // [kk][row_local]
    __shared__ __align__(16) float Bs [4][104];   // [kk][col] (padded)
    __shared__ float biasSh[FIN];

    const int tid = threadIdx.x;
    const int rowBase = blockIdx.x * 128;
    const int rg = tid >> 2;     // 0..31  -> rows rg*4..rg*4+3
    const int cg = tid & 3;      // 0..3   -> cols cg*25..cg*25+24

    if (hasBias) {
        for (int i = tid; i < K; i += 128) biasSh[i] = bias_in[i];
    }

    float acc[4][25];
#pragma unroll
    for (int i = 0; i < 4; i++)
#pragma unroll
        for (int j = 0; j < 25; j++) acc[i][j] = 0.0f;

    const int row = rowBase + tid;
    const bool rowValid = (row < N_NODES_C);
    const float* Arow = A + (size_t)row * K;

    const bool wLoad = (tid < 100);
    const int  kr    = tid / 25;    // 0..3
    const int  cidx  = tid % 25;    // 0..24

    for (int k0 = 0; k0 < K; k0 += 4) {
        // global loads issued early (overlap with previous tile's compute)
        float4 av = make_float4(0.f, 0.f, 0.f, 0.f);
        if (rowValid) av = *reinterpret_cast<const float4*>(Arow + k0);
        float4 wv = make_float4(0.f, 0.f, 0.f, 0.f);
        if (wLoad)
            wv = *reinterpret_cast<const float4*>(W + (size_t)(k0 + kr) * 100 + cidx * 4);

        __syncthreads();   // previous compute done; biasSh ready (1st iter)

        if (hasBias) {
            av.x = fmaxf(av.x + biasSh[k0 + 0], 0.0f);
            av.y = fmaxf(av.y + biasSh[k0 + 1], 0.0f);
            av.z = fmaxf(av.z + biasSh[k0 + 2], 0.0f);
            av.w = fmaxf(av.w + biasSh[k0 + 3], 0.0f);
        }
        Ask[0][tid] = av.x; Ask[1][tid] = av.y;
        Ask[2][tid] = av.z; Ask[3][tid] = av.w;
        if (wLoad)
            *reinterpret_cast<float4*>(&Bs[kr][cidx * 4]) = wv;

        __syncthreads();

#pragma unroll
        for (int kk = 0; kk < 4; kk++) {
            float4 a = *reinterpret_cast<const float4*>(&Ask[kk][rg * 4]);
#pragma unroll
            for (int j = 0; j < 25; j++) {
                float b = Bs[kk][cg * 25 + j];
                acc[0][j] = fmaf(a.x, b, acc[0][j]);
                acc[1][j] = fmaf(a.y, b, acc[1][j]);
                acc[2][j] = fmaf(a.z, b, acc[2][j]);
                acc[3][j] = fmaf(a.w, b, acc[3][j]);
            }
        }
    }

    // epilogue: write xw and self-loop-initialized agg
#pragma unroll
    for (int i = 0; i < 4; i++) {
        int r = rowBase + rg * 4 + i;
        if (r < N_NODES_C) {
            float di = dinv[r];
            float s  = 2.0f * di * di;
            float* xr = xw     + (size_t)r * FDIM + cg * 25;
            float* ar = aggOut + (size_t)r * FDIM + cg * 25;
#pragma unroll
            for (int j = 0; j < 25; j++) {
                float v = acc[i][j];
                xr[j] = v;
                ar[j] = s * v;
            }
        }
    }
}

// ---------------------------------------------------------------------------
// Scatter: for each edge e: agg[col] += dinv[row]*dinv[col] * xw[row]
// Warp per edge (grid-stride); lanes 0..24 each handle one float4 chunk,
// using vectorized red.global.add.v4.f32 (sm_90+).
// ---------------------------------------------------------------------------
__global__ __launch_bounds__(256)
void scatter_kernel(const int* __restrict__ erow,
                    const int* __restrict__ ecol,
                    const float* __restrict__ dinv,
                    const float* __restrict__ xw,
                    float* __restrict__ agg)
{
    const int lane = threadIdx.x & 31;
    int warp = (blockIdx.x * blockDim.x + threadIdx.x) >> 5;
    const int nwarps = (gridDim.x * blockDim.x) >> 5;
    for (int e = warp; e < N_EDGES_C; e += nwarps) {
        const int r = erow[e];
        const int c = ecol[e];
        const float coeff = dinv[r] * dinv[c];
        if (lane < 25) {
            const float4 v = *reinterpret_cast<const float4*>(xw + (size_t)r * FDIM + lane * 4);
            float* p = agg + (size_t)c * FDIM + lane * 4;
            asm volatile("red.global.add.v4.f32 [%0], {%1, %2, %3, %4};"
                         :: "l"(p),
                            "f"(coeff * v.x), "f"(coeff * v.y),
                            "f"(coeff * v.z), "f"(coeff * v.w)
                         : "memory");
        }
    }
}

// ---------------------------------------------------------------------------
// Pool: h5 = relu(agg + b5); sums[batch[i]] += h5[i]; cnt[batch[i]] += 1
// Warp per node.
// ---------------------------------------------------------------------------
__global__ __launch_bounds__(256)
void pool_kernel(const float* __restrict__ agg,
                 const float* __restrict__ b5,
                 const int* __restrict__ batch,
                 float* __restrict__ sums,
                 float* __restrict__ cnt)
{
    const int lane = threadIdx.x & 31;
    const int i = (blockIdx.x * blockDim.x + threadIdx.x) >> 5;
    if (i >= N_NODES_C) return;
    const int g = batch[i];
    if (lane < 25) {
        float4 v  = *reinterpret_cast<const float4*>(agg + (size_t)i * FDIM + lane * 4);
        float4 bv = *reinterpret_cast<const float4*>(b5 + lane * 4);
        v.x = fmaxf(v.x + bv.x, 0.0f);
        v.y = fmaxf(v.y + bv.y, 0.0f);
        v.z = fmaxf(v.z + bv.z, 0.0f);
        v.w = fmaxf(v.w + bv.w, 0.0f);
        float* p = sums + (size_t)g * FDIM + lane * 4;
        asm volatile("red.global.add.v4.f32 [%0], {%1, %2, %3, %4};"
                     :: "l"(p), "f"(v.x), "f"(v.y), "f"(v.z), "f"(v.w)
                     : "memory");
    }
    if (lane == 0) atomicAdd(cnt + g, 1.0f);
}

// ---------------------------------------------------------------------------
// Readout MLP (tiny: 1000 rows). One block per graph.
// ---------------------------------------------------------------------------
__global__ __launch_bounds__(128)
void mlp_first_kernel(const float* __restrict__ sums,
                      const float* __restrict__ cnt,
                      const float* __restrict__ W,
                      const float* __restrict__ b,
                      float* __restrict__ out)
{
    __shared__ float sh[FDIM];
    const int g = blockIdx.x, tid = threadIdx.x;
    if (tid < FDIM) sh[tid] = sums[g * FDIM + tid] / fmaxf(cnt[g], 1.0f);
    __syncthreads();
    if (tid < FDIM) {
        float acc = b[tid];
#pragma unroll 10
        for (int k = 0; k < FDIM; k++)
            acc = fmaf(sh[k], W[k * FDIM + tid], acc);
        out[g * FDIM + tid] = fmaxf(acc, 0.0f);
    }
}

__global__ __launch_bounds__(128)
void mlp_kernel(const float* __restrict__ in,
                const float* __restrict__ W,
                const float* __restrict__ b,
                float* __restrict__ out,
                int dout, int doRelu)
{
    __shared__ float sh[FDIM];
    const int g = blockIdx.x, tid = threadIdx.x;
    if (tid < FDIM) sh[tid] = in[g * FDIM + tid];
    __syncthreads();
    if (tid < dout) {
        float acc = b[tid];
#pragma unroll 10
        for (int k = 0; k < FDIM; k++)
            acc = fmaf(sh[k], W[k * dout + tid], acc);
        out[g * dout + tid] = doRelu ? fmaxf(acc, 0.0f) : acc;
    }
}

// ---------------------------------------------------------------------------
// Launch
// ---------------------------------------------------------------------------
extern "C" void kernel_launch(void* const* d_in, const int* in_sizes, int n_in,
                              void* d_out, int out_size)
{
    const float* x        = (const float*)d_in[0];
    const int*   ei_raw   = (const int*)d_in[1];   // int32 OR int64 (detected)
    const int*   bat_raw  = (const int*)d_in[2];
    const float* W1  = (const float*)d_in[3];  const float* b1  = (const float*)d_in[4];
    const float* W2  = (const float*)d_in[5];  const float* b2  = (const float*)d_in[6];
    const float* W3  = (const float*)d_in[7];  const float* b3  = (const float*)d_in[8];
    const float* W4  = (const float*)d_in[9];  const float* b4  = (const float*)d_in[10];
    const float* W5  = (const float*)d_in[11]; const float* b5  = (const float*)d_in[12];
    const float* Wl1 = (const float*)d_in[13]; const float* bl1 = (const float*)d_in[14];
    const float* Wl2 = (const float*)d_in[15]; const float* bl2 = (const float*)d_in[16];
    const float* Wl3 = (const float*)d_in[17]; const float* bl3 = (const float*)d_in[18];

    float *xw, *aggA, *aggB, *deg, *dinv, *sums, *cnt, *g1, *g2;
    int *erow, *ecol, *bat;
    cudaGetSymbolAddress((void**)&xw,   g_xw);
    cudaGetSymbolAddress((void**)&aggA, g_aggA);
    cudaGetSymbolAddress((void**)&aggB, g_aggB);
    cudaGetSymbolAddress((void**)&deg,  g_deg);
    cudaGetSymbolAddress((void**)&dinv, g_dinv);
    cudaGetSymbolAddress((void**)&sums, g_sums);
    cudaGetSymbolAddress((void**)&cnt,  g_cnt);
    cudaGetSymbolAddress((void**)&g1,   g_g1);
    cudaGetSymbolAddress((void**)&g2,   g_g2);
    cudaGetSymbolAddress((void**)&erow, g_erow);
    cudaGetSymbolAddress((void**)&ecol, g_ecol);
    cudaGetSymbolAddress((void**)&bat,  g_bat);

    // index dtype detection + normalization to int32
    detect_kernel   <<<1, 32>>>(ei_raw);
    cvt_edges_kernel<<<(N_EDGES_C + 255) / 256, 256>>>(ei_raw, erow, ecol);
    cvt_batch_kernel<<<(N_NODES_C + 255) / 256, 256>>>(bat_raw, bat);

    // degree / normalization
    zero_kernel<<<(N_NODES_C + 255) / 256, 256>>>(deg, N_NODES_C);
    deg_kernel <<<(N_EDGES_C + 255) / 256, 256>>>(ecol, deg);
    dinv_kernel<<<(N_NODES_C + 255) / 256, 256>>>(deg, dinv);

    const int GB = (N_NODES_C + 127) / 128;   // GEMM blocks
    const int SB = 4736;                      // scatter blocks (grid-stride)

    // Layer 1 (K=336, input = raw x, no input bias/relu)
    gemm_kernel   <<<GB, 128>>>(x,    W1, nullptr, dinv, xw, aggA, FIN, 0);
    scatter_kernel<<<SB, 256>>>(erow, ecol, dinv, xw, aggA);
    // Layers 2..5 (K=100); previous bias+relu fused into GEMM A-load
    gemm_kernel   <<<GB, 128>>>(aggA, W2, b1, dinv, xw, aggB, FDIM, 1);
    scatter_kernel<<<SB, 256>>>(erow, ecol, dinv, xw, aggB);
    gemm_kernel   <<<GB, 128>>>(aggB, W3, b2, dinv, xw, aggA, FDIM, 1);
    scatter_kernel<<<SB, 256>>>(erow, ecol, dinv, xw, aggA);
    gemm_kernel   <<<GB, 128>>>(aggA, W4, b3, dinv, xw, aggB, FDIM, 1);
    scatter_kernel<<<SB, 256>>>(erow, ecol, dinv, xw, aggB);
    gemm_kernel   <<<GB, 128>>>(aggB, W5, b4, dinv, xw, aggA, FDIM, 1);
    scatter_kernel<<<SB, 256>>>(erow, ecol, dinv, xw, aggA);

    // mean pool (bias+relu of layer 5 fused here)
    zero_kernel<<<(N_GRAPHS_C * FDIM + 255) / 256, 256>>>(sums, N_GRAPHS_C * FDIM);
    zero_kernel<<<(N_GRAPHS_C + 255) / 256, 256>>>(cnt, N_GRAPHS_C);
    {
        long long threads = (long long)N_NODES_C * 32;
        int blocks = (int)((threads + 255) / 256);
        pool_kernel<<<blocks, 256>>>(aggA, b5, bat, sums, cnt);
    }

    // readout MLP
    mlp_first_kernel<<<N_GRAPHS_C, 128>>>(sums, cnt, Wl1, bl1, g1);
    mlp_kernel      <<<N_GRAPHS_C, 128>>>(g1, Wl2, bl2, g2, FDIM, 1);
    mlp_kernel      <<<N_GRAPHS_C, 128>>>(g2, Wl3, bl3, (float*)d_out, 29, 0);
}

// round 10
// speedup vs baseline: 1.1487x; 1.1487x over previous
#include <cuda_runtime.h>
#include <cuda_bf16.h>
#include <math.h>

// Problem constants (match reference)
#define N_NODES_C  100000
#define N_EDGES_C  1600000
#define N_GRAPHS_C 1000
#define FDIM       100
#define FIN        336
#define NBLK256    ((N_NODES_C + 255) / 256)   // 391

// ---------------------------------------------------------------------------
// Scratch buffers (static __device__ globals — no runtime allocation)
// ---------------------------------------------------------------------------
__device__ __align__(16) float g_xw  [N_NODES_C * FDIM];   // h @ W for current layer
__device__ __align__(16) float g_agg [N_NODES_C * FDIM];   // aggregated output
__device__ __align__(16) float g_dinv[N_NODES_C];
__device__ __align__(16) float g_sums[N_GRAPHS_C * FDIM];
__device__ __align__(16) float g_cnt [N_GRAPHS_C];
__device__ __align__(16) float g_g1  [N_GRAPHS_C * FDIM];
__device__ __align__(16) float g_g2  [N_GRAPHS_C * FDIM];
__device__ __align__(16) int   g_erow[N_EDGES_C];
__device__ __align__(16) int   g_ecol[N_EDGES_C];
__device__ __align__(16) int   g_srow[N_EDGES_C];          // CSR: row indices sorted by col
__device__ __align__(16) int   g_colstart[N_NODES_C + 1];  // CSR offsets
__device__ __align__(16) int   g_cnti[N_NODES_C];          // per-col edge counts
__device__ __align__(16) int   g_fill[N_NODES_C];          // fill cursors
__device__ __align__(16) int   g_bat [N_NODES_C];
__device__ int g_blocksum[NBLK256];
__device__ int g_blockoff[NBLK256];
__device__ int g_is64;

// ---------------------------------------------------------------------------
// Index dtype detection + normalization to int32 (JAX may give int32 or int64)
// ---------------------------------------------------------------------------
__global__ void detect_kernel(const int* __restrict__ raw) {
    if (blockIdx.x == 0 && threadIdx.x == 0) {
        int s = 0;
        for (int i = 0; i < 64; i++) s |= raw[2 * i + 1];
        g_is64 = (s == 0) ? 1 : 0;
    }
}

__global__ void cvt_edges_kernel(const int* __restrict__ raw,
                                 int* __restrict__ erow,
                                 int* __restrict__ ecol) {
    int e = blockIdx.x * blockDim.x + threadIdx.x;
    if (e >= N_EDGES_C) return;
    if (g_is64) {
        erow[e] = raw[2 * e];
        ecol[e] = raw[2 * (N_EDGES_C + e)];
    } else {
        erow[e] = raw[e];
        ecol[e] = raw[N_EDGES_C + e];
    }
}

__global__ void cvt_batch_kernel(const int* __restrict__ raw,
                                 int* __restrict__ bat) {
    int i = blockIdx.x * blockDim.x + threadIdx.x;
    if (i >= N_NODES_C) return;
    bat[i] = g_is64 ? raw[2 * i] : raw[i];
}

// ---------------------------------------------------------------------------
// Utility
// ---------------------------------------------------------------------------
__global__ void zero_f_kernel(float* __restrict__ p, int n) {
    int i = blockIdx.x * blockDim.x + threadIdx.x;
    if (i < n) p[i] = 0.0f;
}
__global__ void zero_i_kernel(int* __restrict__ p, int n) {
    int i = blockIdx.x * blockDim.x + threadIdx.x;
    if (i < n) p[i] = 0;
}

// ---------------------------------------------------------------------------
// CSR build: count -> scan (3 kernels) -> fill
// ---------------------------------------------------------------------------
__global__ void count_kernel(const int* __restrict__ ecol,
                             int* __restrict__ cnti) {
    int e = blockIdx.x * blockDim.x + threadIdx.x;
    if (e < N_EDGES_C) atomicAdd(cnti + ecol[e], 1);
}

__global__ void scanA_kernel(const int* __restrict__ cnti,
                             int* __restrict__ blocksum) {
    __shared__ int sh[256];
    int t = threadIdx.x, b = blockIdx.x;
    int i = b * 256 + t;
    int v = (i < N_NODES_C) ? cnti[i] : 0;
    sh[t] = v;
    __syncthreads();
    for (int off = 128; off > 0; off >>= 1) {
        if (t < off) sh[t] += sh[t + off];
        __syncthreads();
    }
    if (t == 0) blocksum[b] = sh[0];
}

__global__ void scanB_kernel(const int* __restrict__ blocksum,
                             int* __restrict__ blockoff,
                             int* __restrict__ colstart) {
    if (threadIdx.x == 0) {
        int acc = 0;
        for (int b = 0; b < NBLK256; b++) {
            blockoff[b] = acc;
            acc += blocksum[b];
        }
        colstart[N_NODES_C] = acc;
    }
}

__global__ void scanC_kernel(const int* __restrict__ cnti,
                             const int* __restrict__ blockoff,
                             int* __restrict__ colstart,
                             float* __restrict__ dinv) {
    __shared__ int sh[256];
    int t = threadIdx.x, b = blockIdx.x;
    int i = b * 256 + t;
    int v = (i < N_NODES_C) ? cnti[i] : 0;
    sh[t] = v;
    __syncthreads();
    // Hillis-Steele inclusive scan
    for (int off = 1; off < 256; off <<= 1) {
        int x = (t >= off) ? sh[t - off] : 0;
        __syncthreads();
        sh[t] += x;
        __syncthreads();
    }
    if (i < N_NODES_C) {
        colstart[i] = blockoff[b] + sh[t] - v;   // exclusive
        dinv[i] = rsqrtf((float)v + 2.0f);
    }
}

__global__ void fill_kernel(const int* __restrict__ erow,
                            const int* __restrict__ ecol,
                            const int* __restrict__ colstart,
                            int* __restrict__ fill,
                            int* __restrict__ srow) {
    int e = blockIdx.x * blockDim.x + threadIdx.x;
    if (e >= N_EDGES_C) return;
    int c = ecol[e];
    int pos = colstart[c] + atomicAdd(fill + c, 1);
    srow[pos] = erow[e];
}

// ---------------------------------------------------------------------------
// GEMM:  xw[N,100] = f(A)[N,K] @ W[K,100]   (f = relu(.+bias_in) when hasBias)
// BM=128, BN=100, BK=4; 128 threads; thread (rg,cg) owns 4 rows x 25 cols.
// Inner loop uses packed fma.rn.f32x2: row-pairs packed in 64-bit accums,
// W pre-broadcast into float2{b,b} in shared so b operand is a single LDS.64.
// ---------------------------------------------------------------------------
__global__ __launch_bounds__(128)
void gemm_kernel(const float* __restrict__ A,
                 const float* __restrict__ W,
                 const float* __restrict__ bias_in,
                 float* __restrict__ xw,
                 int K, int hasBias)
{
    __shared__ __align__(16) float  Ask[4][128];   // [kk][row_local]
    __shared__ __align__(16) float2 Bs2[4][104];   // [kk][col] = {b, b}
    __shared__ float biasSh[FIN];

    const int tid = threadIdx.x;
    const int rowBase = blockIdx.x * 128;
    const int rg = tid >> 2;     // 0..31 -> rows rg*4..rg*4+3
    const int cg = tid & 3;      // 0..3  -> cols cg*25..cg*25+24

    if (hasBias) {
        for (int i = tid; i < K; i += 128) biasSh[i] = bias_in[i];
    }

    unsigned long long acc0[25], acc1[25];   // packed {row0,row1}, {row2,row3}
#pragma unroll
    for (int j = 0; j < 25; j++) { acc0[j] = 0ULL; acc1[j] = 0ULL; }

    const int row = rowBase + tid;
    const bool rowValid = (row < N_NODES_C);
    const float* Arow = A + (size_t)row * K;

    const bool wLoad = (tid < 100);
    const int  kr    = tid / 25;    // 0..3
    const int  cidx  = tid % 25;    // 0..24

    for (int k0 = 0; k0 < K; k0 += 4) {
        float4 av = make_float4(0.f, 0.f, 0.f, 0.f);
        if (rowValid) av = *reinterpret_cast<const float4*>(Arow + k0);
        float4 wv = make_float4(0.f, 0.f, 0.f, 0.f);
        if (wLoad)
            wv = *reinterpret_cast<const float4*>(W + (size_t)(k0 + kr) * 100 + cidx * 4);

        __syncthreads();   // previous tile's compute done; biasSh ready (1st iter)

        if (hasBias) {
            av.x = fmaxf(av.x + biasSh[k0 + 0], 0.0f);
            av.y = fmaxf(av.y + biasSh[k0 + 1], 0.0f);
            av.z = fmaxf(av.z + biasSh[k0 + 2], 0.0f);
            av.w = fmaxf(av.w + biasSh[k0 + 3], 0.0f);
        }
        Ask[0][tid] = av.x; Ask[1][tid] = av.y;
        Ask[2][tid] = av.z; Ask[3][tid] = av.w;
        if (wLoad) {
            Bs2[kr][cidx * 4 + 0] = make_float2(wv.x, wv.x);
            Bs2[kr][cidx * 4 + 1] = make_float2(wv.y, wv.y);
            Bs2[kr][cidx * 4 + 2] = make_float2(wv.z, wv.z);
            Bs2[kr][cidx * 4 + 3] = make_float2(wv.w, wv.w);
        }

        __syncthreads();

#pragma unroll
        for (int kk = 0; kk < 4; kk++) {
            unsigned long long a01 =
                *reinterpret_cast<const unsigned long long*>(&Ask[kk][rg * 4]);
            unsigned long long a23 =
                *reinterpret_cast<const unsigned long long*>(&Ask[kk][rg * 4 + 2]);
#pragma unroll
            for (int j = 0; j < 25; j++) {
                unsigned long long bb =
                    *reinterpret_cast<const unsigned long long*>(&Bs2[kk][cg * 25 + j]);
                asm("fma.rn.f32x2 %0, %1, %2, %0;"
                    : "+l"(acc0[j]) : "l"(a01), "l"(bb));
                asm("fma.rn.f32x2 %0, %1, %2, %0;"
                    : "+l"(acc1[j]) : "l"(a23), "l"(bb));
            }
        }
    }

    // epilogue: unpack and store xw rows
    const int r0 = rowBase + rg * 4;
    const bool v0 = (r0 + 0) < N_NODES_C;
    const bool v1 = (r0 + 1) < N_NODES_C;
    const bool v2 = (r0 + 2) < N_NODES_C;
    const bool v3 = (r0 + 3) < N_NODES_C;
    float* p0 = xw + (size_t)(r0 + 0) * FDIM + cg * 25;
    float* p1 = xw + (size_t)(r0 + 1) * FDIM + cg * 25;
    float* p2 = xw + (size_t)(r0 + 2) * FDIM + cg * 25;
    float* p3 = xw + (size_t)(r0 + 3) * FDIM + cg * 25;
#pragma unroll
    for (int j = 0; j < 25; j++) {
        float lo0, hi0, lo1, hi1;
        asm("mov.b64 {%0, %1}, %2;" : "=f"(lo0), "=f"(hi0) : "l"(acc0[j]));
        asm("mov.b64 {%0, %1}, %2;" : "=f"(lo1), "=f"(hi1) : "l"(acc1[j]));
        if (v0) p0[j] = lo0;
        if (v1) p1[j] = hi0;
        if (v2) p2[j] = lo1;
        if (v3) p3[j] = hi1;
    }
}

// ---------------------------------------------------------------------------
// Aggregation (CSR gather, no atomics): warp per node c:
//   agg[c] = sum_{e in in(c)} dinv[row_e]*dinv[c] * xw[row_e]  +  2*dinv[c]^2 * xw[c]
// Lanes 0..24 each own one float4 chunk of the 100-dim feature.
// ---------------------------------------------------------------------------
__global__ __launch_bounds__(256)
void agg_kernel(const int* __restrict__ colstart,
                const int* __restrict__ srow,
                const float* __restrict__ dinv,
                const float* __restrict__ xw,
                float* __restrict__ agg)
{
    const int lane = threadIdx.x & 31;
    const int c = (blockIdx.x * blockDim.x + threadIdx.x) >> 5;
    if (c >= N_NODES_C) return;
    const int s = colstart[c];
    const int eEnd = colstart[c + 1];
    if (lane >= 25) return;

    const float dc = dinv[c];
    float4 acc = make_float4(0.f, 0.f, 0.f, 0.f);
    for (int e = s; e < eEnd; e++) {
        const int r = __ldg(srow + e);                 // broadcast across warp
        const float w = dc * __ldg(dinv + r);          // broadcast
        const float4 v =
            *reinterpret_cast<const float4*>(xw + (size_t)r * FDIM + lane * 4);
        acc.x = fmaf(w, v.x, acc.x);
        acc.y = fmaf(w, v.y, acc.y);
        acc.z = fmaf(w, v.z, acc.z);
        acc.w = fmaf(w, v.w, acc.w);
    }
    // self-loop (fill weight 2)
    const float ws = 2.0f * dc * dc;
    const float4 vs =
        *reinterpret_cast<const float4*>(xw + (size_t)c * FDIM + lane * 4);
    acc.x = fmaf(ws, vs.x, acc.x);
    acc.y = fmaf(ws, vs.y, acc.y);
    acc.z = fmaf(ws, vs.z, acc.z);
    acc.w = fmaf(ws, vs.w, acc.w);
    *reinterpret_cast<float4*>(agg + (size_t)c * FDIM + lane * 4) = acc;
}

// ---------------------------------------------------------------------------
// Pool: h5 = relu(agg + b5); sums[batch[i]] += h5[i]; cnt[batch[i]] += 1
// ---------------------------------------------------------------------------
__global__ __launch_bounds__(256)
void pool_kernel(const float* __restrict__ agg,
                 const float* __restrict__ b5,
                 const int* __restrict__ batch,
                 float* __restrict__ sums,
                 float* __restrict__ cnt)
{
    const int lane = threadIdx.x & 31;
    const int i = (blockIdx.x * blockDim.x + threadIdx.x) >> 5;
    if (i >= N_NODES_C) return;
    const int g = batch[i];
    if (lane < 25) {
        float4 v  = *reinterpret_cast<const float4*>(agg + (size_t)i * FDIM + lane * 4);
        float4 bv = *reinterpret_cast<const float4*>(b5 + lane * 4);
        v.x = fmaxf(v.x + bv.x, 0.0f);
        v.y = fmaxf(v.y + bv.y, 0.0f);
        v.z = fmaxf(v.z + bv.z, 0.0f);
        v.w = fmaxf(v.w + bv.w, 0.0f);
        float* p = sums + (size_t)g * FDIM + lane * 4;
        asm volatile("red.global.add.v4.f32 [%0], {%1, %2, %3, %4};"
                     :: "l"(p), "f"(v.x), "f"(v.y), "f"(v.z), "f"(v.w)
                     : "memory");
    }
    if (lane == 0) atomicAdd(cnt + g, 1.0f);
}

// ---------------------------------------------------------------------------
// Readout MLP (tiny: 1000 graphs). One block per graph.
// ---------------------------------------------------------------------------
__global__ __launch_bounds__(128)
void mlp_first_kernel(const float* __restrict__ sums,
                      const float* __restrict__ cnt,
                      const float* __restrict__ W,
                      const float* __restrict__ b,
                      float* __restrict__ out)
{
    __shared__ float sh[FDIM];
    const int g = blockIdx.x, tid = threadIdx.x;
    if (tid < FDIM) sh[tid] = sums[g * FDIM + tid] / fmaxf(cnt[g], 1.0f);
    __syncthreads();
    if (tid < FDIM) {
        float acc = b[tid];
#pragma unroll 10
        for (int k = 0; k < FDIM; k++)
            acc = fmaf(sh[k], W[k * FDIM + tid], acc);
        out[g * FDIM + tid] = fmaxf(acc, 0.0f);
    }
}

__global__ __launch_bounds__(128)
void mlp_kernel(const float* __restrict__ in,
                const float* __restrict__ W,
                const float* __restrict__ b,
                float* __restrict__ out,
                int dout, int doRelu)
{
    __shared__ float sh[FDIM];
    const int g = blockIdx.x, tid = threadIdx.x;
    if (tid < FDIM) sh[tid] = in[g * FDIM + tid];
    __syncthreads();
    if (tid < dout) {
        float acc = b[tid];
#pragma unroll 10
        for (int k = 0; k < FDIM; k++)
            acc = fmaf(sh[k], W[k * dout + tid], acc);
        out[g * dout + tid] = doRelu ? fmaxf(acc, 0.0f) : acc;
    }
}

// ---------------------------------------------------------------------------
// Launch
// ---------------------------------------------------------------------------
extern "C" void kernel_launch(void* const* d_in, const int* in_sizes, int n_in,
                              void* d_out, int out_size)
{
    const float* x       = (const float*)d_in[0];
    const int*   ei_raw  = (const int*)d_in[1];   // int32 OR int64 (detected)
    const int*   bat_raw = (const int*)d_in[2];
    const float* W1  = (const float*)d_in[3];  const float* b1  = (const float*)d_in[4];
    const float* W2  = (const float*)d_in[5];  const float* b2  = (const float*)d_in[6];
    const float* W3  = (const float*)d_in[7];  const float* b3  = (const float*)d_in[8];
    const float* W4  = (const float*)d_in[9];  const float* b4  = (const float*)d_in[10];
    const float* W5  = (const float*)d_in[11]; const float* b5  = (const float*)d_in[12];
    const float* Wl1 = (const float*)d_in[13]; const float* bl1 = (const float*)d_in[14];
    const float* Wl2 = (const float*)d_in[15]; const float* bl2 = (const float*)d_in[16];
    const float* Wl3 = (const float*)d_in[17]; const float* bl3 = (const float*)d_in[18];

    float *xw, *agg, *dinv, *sums, *cnt, *g1, *g2;
    int *erow, *ecol, *srow, *colstart, *cnti, *fill, *bat, *bsum, *boff;
    cudaGetSymbolAddress((void**)&xw,   g_xw);
    cudaGetSymbolAddress((void**)&agg,  g_agg);
    cudaGetSymbolAddress((void**)&dinv, g_dinv);
    cudaGetSymbolAddress((void**)&sums, g_sums);
    cudaGetSymbolAddress((void**)&cnt,  g_cnt);
    cudaGetSymbolAddress((void**)&g1,   g_g1);
    cudaGetSymbolAddress((void**)&g2,   g_g2);
    cudaGetSymbolAddress((void**)&erow, g_erow);
    cudaGetSymbolAddress((void**)&ecol, g_ecol);
    cudaGetSymbolAddress((void**)&srow, g_srow);
    cudaGetSymbolAddress((void**)&colstart, g_colstart);
    cudaGetSymbolAddress((void**)&cnti, g_cnti);
    cudaGetSymbolAddress((void**)&fill, g_fill);
    cudaGetSymbolAddress((void**)&bat,  g_bat);
    cudaGetSymbolAddress((void**)&bsum, g_blocksum);
    cudaGetSymbolAddress((void**)&boff, g_blockoff);

    const int EB = (N_EDGES_C + 255) / 256;

    // index dtype detection + normalization to int32
    detect_kernel   <<<1, 32>>>(ei_raw);
    cvt_edges_kernel<<<EB, 256>>>(ei_raw, erow, ecol);
    cvt_batch_kernel<<<NBLK256, 256>>>(bat_raw, bat);

    // CSR build (also yields degree -> dinv)
    zero_i_kernel<<<NBLK256, 256>>>(cnti, N_NODES_C);
    count_kernel <<<EB, 256>>>(ecol, cnti);
    scanA_kernel <<<NBLK256, 256>>>(cnti, bsum);
    scanB_kernel <<<1, 32>>>(bsum, boff, colstart);
    scanC_kernel <<<NBLK256, 256>>>(cnti, boff, colstart, dinv);
    zero_i_kernel<<<NBLK256, 256>>>(fill, N_NODES_C);
    fill_kernel  <<<EB, 256>>>(erow, ecol, colstart, fill, srow);

    const int GB = (N_NODES_C + 127) / 128;            // GEMM blocks
    const int AB = (N_NODES_C * 32 + 255) / 256;       // agg blocks (warp/node)

    // Layer 1 (K=336, raw input, no fused bias/relu)
    gemm_kernel<<<GB, 128>>>(x,   W1, nullptr, xw, FIN, 0);
    agg_kernel <<<AB, 256>>>(colstart, srow, dinv, xw, agg);
    // Layers 2..5 (K=100); previous layer's bias+relu fused into GEMM A-load
    gemm_kernel<<<GB, 128>>>(agg, W2, b1, xw, FDIM, 1);
    agg_kernel <<<AB, 256>>>(colstart, srow, dinv, xw, agg);
    gemm_kernel<<<GB, 128>>>(agg, W3, b2, xw, FDIM, 1);
    agg_kernel <<<AB, 256>>>(colstart, srow, dinv, xw, agg);
    gemm_kernel<<<GB, 128>>>(agg, W4, b3, xw, FDIM, 1);
    agg_kernel <<<AB, 256>>>(colstart, srow, dinv, xw, agg);
    gemm_kernel<<<GB, 128>>>(agg, W5, b4, xw, FDIM, 1);
    agg_kernel <<<AB, 256>>>(colstart, srow, dinv, xw, agg);

    // mean pool (bias+relu of layer 5 fused here)
    zero_f_kernel<<<(N_GRAPHS_C * FDIM + 255) / 256, 256>>>(sums, N_GRAPHS_C * FDIM);
    zero_f_kernel<<<(N_GRAPHS_C + 255) / 256, 256>>>(cnt, N_GRAPHS_C);
    pool_kernel<<<AB, 256>>>(agg, b5, bat, sums, cnt);

    // readout MLP
    mlp_first_kernel<<<N_GRAPHS_C, 128>>>(sums, cnt, Wl1, bl1, g1);
    mlp_kernel      <<<N_GRAPHS_C, 128>>>(g1, Wl2, bl2, g2, FDIM, 1);
    mlp_kernel      <<<N_GRAPHS_C, 128>>>(g2, Wl3, bl3, (float*)d_out, 29, 0);
}